// round 13
// baseline (speedup 1.0000x reference)
#include <cuda_runtime.h>
#include <cuda_bf16.h>
#include <cstdint>

// ---------------------------------------------------------------------------
// SparseCoder (TopK SAE) forward, GB300 sm_103a
// Round 13: revert to Round-10 verified GEMM pipeline (BK=128/NSTG=2,
// __syncthreads 2-stage cp.async). Add epilogue candidate extraction
// (values >= 2.0 -> per-row global lists) so k_topk becomes a short-list
// radix select instead of re-reading 256 MB. Full-histogram fallback kept.
// ---------------------------------------------------------------------------

#define B_ROWS 4096
#define D_IN   2048
#define N_LAT  32768
#define KSEL   32
#define NCAND  48
#define LCAP   2048

#define OFF_ACT  (B_ROWS * D_IN)
#define OFF_IDX  (OFF_ACT + B_ROWS * KSEL)
#define OFF_SC   (OFF_IDX + B_ROWS * KSEL)

// ------------------------- device scratch ----------------------------------
__device__ __nv_bfloat16 g_xb16[(size_t)B_ROWS * D_IN];     // 16 MB
__device__ __nv_bfloat16 g_wb16[(size_t)N_LAT * D_IN];      // 128 MB
__device__ __nv_bfloat16 g_pre [(size_t)B_ROWS * N_LAT];    // 256 MB
__device__ unsigned g_list[(size_t)B_ROWS * LCAP];          // 32 MB
__device__ int    g_cnt [B_ROWS];
__device__ int    g_cand[B_ROWS * NCAND];
__device__ float  g_cval[B_ROWS * NCAND];
__device__ int    g_tidx[B_ROWS * KSEL];
__device__ float  g_tact[B_ROWS * KSEL];
__device__ float  g_colsum[D_IN];
__device__ double g_err2;
__device__ double g_sumsq;

// ------------------------- init --------------------------------------------
__global__ void k_init() {
    int i = blockIdx.x * blockDim.x + threadIdx.x;
    if (i < D_IN) g_colsum[i] = 0.f;
    if (i < B_ROWS) g_cnt[i] = 0;
    if (i == 0) { g_err2 = 0.0; g_sumsq = 0.0; }
}

// ------------------------- bf16 conversions --------------------------------
__global__ void k_conv_x(const float* __restrict__ x, const float* __restrict__ b_dec) {
    int i4 = blockIdx.x * blockDim.x + threadIdx.x;
    if (i4 >= B_ROWS * (D_IN / 4)) return;
    int c4 = i4 & (D_IN / 4 - 1);
    float4 v = ((const float4*)x)[i4];
    float4 b = ((const float4*)b_dec)[c4];
    __nv_bfloat162 lo = __floats2bfloat162_rn(v.x - b.x, v.y - b.y);
    __nv_bfloat162 hi = __floats2bfloat162_rn(v.z - b.z, v.w - b.w);
    uint2 u;
    u.x = *(unsigned int*)&lo;
    u.y = *(unsigned int*)&hi;
    ((uint2*)g_xb16)[i4] = u;
}

__global__ void k_conv_w(const float* __restrict__ W) {
    int i4 = blockIdx.x * blockDim.x + threadIdx.x;
    if (i4 >= N_LAT * (D_IN / 4)) return;
    float4 v = ((const float4*)W)[i4];
    __nv_bfloat162 lo = __floats2bfloat162_rn(v.x, v.y);
    __nv_bfloat162 hi = __floats2bfloat162_rn(v.z, v.w);
    uint2 u;
    u.x = *(unsigned int*)&lo;
    u.y = *(unsigned int*)&hi;
    ((uint2*)g_wb16)[i4] = u;
}

// ------------------------- screening GEMM (mma.sync, pipelined) ------------
#define BM 128
#define BN 256
#define BK 128
#define NSTG 2
#define NT (D_IN / BK)            // 16 k-tiles
#define SP 136                    // smem row stride in bf16 (272 B, conflict-free ldmatrix)
#define AS_ELE (BM * SP)          // 17408
#define BS_ELE (BN * SP)          // 34816
#define STG_ELE (AS_ELE + BS_ELE) // 52224 elems = 104448 B
#define GEMM_SMEM (NSTG * STG_ELE * 2)   // 208896 B

__device__ __forceinline__ void ldsm4(unsigned int* r, const void* p) {
    unsigned int a = (unsigned int)__cvta_generic_to_shared(p);
    asm volatile("ldmatrix.sync.aligned.m8n8.x4.shared.b16 {%0,%1,%2,%3}, [%4];"
                 : "=r"(r[0]), "=r"(r[1]), "=r"(r[2]), "=r"(r[3]) : "r"(a));
}

__device__ __forceinline__ void mma16816(float* d, const unsigned int* a, const unsigned int* b) {
    asm volatile("mma.sync.aligned.m16n8k16.row.col.f32.bf16.bf16.f32 "
                 "{%0,%1,%2,%3},{%4,%5,%6,%7},{%8,%9},{%0,%1,%2,%3};"
                 : "+f"(d[0]), "+f"(d[1]), "+f"(d[2]), "+f"(d[3])
                 : "r"(a[0]), "r"(a[1]), "r"(a[2]), "r"(a[3]), "r"(b[0]), "r"(b[1]));
}

__device__ __forceinline__ void cp16(void* dst, const void* src) {
    unsigned int d = (unsigned int)__cvta_generic_to_shared(dst);
    asm volatile("cp.async.cg.shared.global [%0], [%1], 16;" :: "r"(d), "l"(src) : "memory");
}
#define CP_COMMIT() asm volatile("cp.async.commit_group;" ::: "memory")
#define CP_WAIT0()  asm volatile("cp.async.wait_group 0;" ::: "memory")

__global__ __launch_bounds__(256, 1) void k_gemm(const float* __restrict__ b_enc) {
    extern __shared__ __align__(16) __nv_bfloat16 smem[];   // [NSTG][STG_ELE]
    const int m0 = blockIdx.x * BM;       // 32 m-blocks (fast dim)
    const int n0 = blockIdx.y * BN;       // 128 n-blocks
    const int tid = threadIdx.x;
    const int lane = tid & 31, wid = tid >> 5;
    const int wm = (wid & 1) << 6;        // warp row offset (2 warps in m, 64 each)
    const int wn = (wid >> 1) << 6;       // warp col offset (4 warps in n, 64 each)

    float acc[4][8][4];
#pragma unroll
    for (int i = 0; i < 4; i++)
#pragma unroll
        for (int j = 0; j < 8; j++)
#pragma unroll
            for (int q = 0; q < 4; q++) acc[i][j][q] = 0.f;

    // stage loader: 6144 chunks of 16B (A: 2048, B: 4096), 24 per thread
    auto load_stage = [&](int kt, int stg) {
        __nv_bfloat16* s = smem + stg * STG_ELE;
        const int k0 = kt * BK;
#pragma unroll
        for (int i = 0; i < 24; i++) {
            int c = tid + i * 256;
            if (c < 2048) {
                int r = c >> 4, q = c & 15;
                cp16(s + r * SP + q * 8,
                     g_xb16 + (size_t)(m0 + r) * D_IN + k0 + q * 8);
            } else {
                int j = c - 2048;
                int r = j >> 4, q = j & 15;
                cp16(s + AS_ELE + r * SP + q * 8,
                     g_wb16 + (size_t)(n0 + r) * D_IN + k0 + q * 8);
            }
        }
        CP_COMMIT();
    };

    load_stage(0, 0);

    const int rowA = (lane & 15);
    const int colA = (lane >> 4) << 3;
    const int rowB = ((lane >> 4) << 3) + (lane & 7);
    const int colB = ((lane >> 3) & 1) << 3;

    for (int kt = 0; kt < NT; kt++) {
        // tile kt's cp.asyncs (issued one full tile ago) complete
        CP_WAIT0();
        // publish them to all threads; also proves every warp finished
        // computing tile kt-1 -> stage (kt+1)&1 is free to overwrite
        __syncthreads();
        if (kt + 1 < NT) load_stage(kt + 1, (kt + 1) & 1);

        const __nv_bfloat16* sA = smem + (kt & 1) * STG_ELE;
        const __nv_bfloat16* sB = sA + AS_ELE;

        unsigned int af[2][4][4], bfr[2][4][4];
#pragma unroll
        for (int mf = 0; mf < 4; mf++)
            ldsm4(af[0][mf], &sA[(wm + mf * 16 + rowA) * SP + colA]);
#pragma unroll
        for (int pr = 0; pr < 4; pr++)
            ldsm4(bfr[0][pr], &sB[(wn + pr * 16 + rowB) * SP + colB]);

#pragma unroll
        for (int s = 0; s < 8; s++) {
            const int cur = s & 1;
            if (s < 7) {
                const int nb = (s + 1) & 1;
                const int kk = (s + 1) * 16;
#pragma unroll
                for (int mf = 0; mf < 4; mf++)
                    ldsm4(af[nb][mf], &sA[(wm + mf * 16 + rowA) * SP + kk + colA]);
#pragma unroll
                for (int pr = 0; pr < 4; pr++)
                    ldsm4(bfr[nb][pr], &sB[(wn + pr * 16 + rowB) * SP + kk + colB]);
            }
#pragma unroll
            for (int mf = 0; mf < 4; mf++)
#pragma unroll
                for (int nf = 0; nf < 8; nf++)
                    mma16816(acc[mf][nf], af[cur][mf], &bfr[cur][nf >> 1][(nf & 1) * 2]);
        }
    }

    // epilogue: + b_enc, relu, bf16 store to g_pre + candidate extraction
#pragma unroll
    for (int mf = 0; mf < 4; mf++) {
        int r0 = m0 + wm + mf * 16 + (lane >> 2);
#pragma unroll
        for (int nf = 0; nf < 8; nf++) {
            int c0 = n0 + wn + nf * 8 + ((lane & 3) << 1);
            float2 be = *(const float2*)(b_enc + c0);
            float v0 = acc[mf][nf][0] + be.x; v0 = v0 > 0.f ? v0 : 0.f;
            float v1 = acc[mf][nf][1] + be.y; v1 = v1 > 0.f ? v1 : 0.f;
            float v2 = acc[mf][nf][2] + be.x; v2 = v2 > 0.f ? v2 : 0.f;
            float v3 = acc[mf][nf][3] + be.y; v3 = v3 > 0.f ? v3 : 0.f;
            __nv_bfloat162 p0 = __floats2bfloat162_rn(v0, v1);
            __nv_bfloat162 p1 = __floats2bfloat162_rn(v2, v3);
            *(__nv_bfloat162*)&g_pre[(size_t)r0 * N_LAT + c0] = p0;
            *(__nv_bfloat162*)&g_pre[(size_t)(r0 + 8) * N_LAT + c0] = p1;
            unsigned pu0 = *(unsigned*)&p0;   // lo = bf16(v0), hi = bf16(v1)
            unsigned pu1 = *(unsigned*)&p1;   // lo = bf16(v2), hi = bf16(v3)
            if (v0 >= 2.0f) {
                int p = atomicAdd(&g_cnt[r0], 1);
                if (p < LCAP) g_list[(size_t)r0 * LCAP + p] = (pu0 << 16) | (unsigned)c0;
            }
            if (v1 >= 2.0f) {
                int p = atomicAdd(&g_cnt[r0], 1);
                if (p < LCAP) g_list[(size_t)r0 * LCAP + p] = (pu0 & 0xFFFF0000u) | (unsigned)(c0 + 1);
            }
            if (v2 >= 2.0f) {
                int p = atomicAdd(&g_cnt[r0 + 8], 1);
                if (p < LCAP) g_list[(size_t)(r0 + 8) * LCAP + p] = (pu1 << 16) | (unsigned)c0;
            }
            if (v3 >= 2.0f) {
                int p = atomicAdd(&g_cnt[r0 + 8], 1);
                if (p < LCAP) g_list[(size_t)(r0 + 8) * LCAP + p] = (pu1 & 0xFFFF0000u) | (unsigned)(c0 + 1);
            }
        }
    }
}

// ------------------------- top-48 candidates -------------------------------
__device__ __forceinline__ unsigned int bkey(unsigned int u) {
    return (u & 0x8000u) ? (u ^ 0xFFFFu) : (u ^ 0x8000u);
}

__global__ void k_topk(void) {
    const int row = blockIdx.x;
    const int tid = threadIdx.x;          // 256
    __shared__ unsigned int list[LCAP];
    __shared__ unsigned int hist[256];
    __shared__ int sB, sAbove, sL, sStrict, cA, cT;

    const int n = g_cnt[row];
    hist[tid] = 0u;
    __syncthreads();

    if (n >= NCAND && n <= LCAP) {
        // ---- fast path: short-list radix select from g_list ----
        const unsigned* gl = g_list + (size_t)row * LCAP;
        for (int i = tid; i < n; i += 256) {
            unsigned e = gl[i];
            list[i] = e;
            atomicAdd(&hist[e >> 24], 1u);
        }
        __syncthreads();
        if (tid == 0) {
            int c = 0, b = 255;
            for (; b >= 0; b--) {
                if (c + (int)hist[b] >= NCAND) break;
                c += (int)hist[b];
            }
            sB = b; sAbove = c;
        }
        __syncthreads();
        const int B = sB, above = sAbove;
        hist[tid] = 0u;
        __syncthreads();
        for (int i = tid; i < n; i += 256) {
            unsigned int k = list[i] >> 16;
            if ((int)(k >> 8) == B) atomicAdd(&hist[k & 255u], 1u);
        }
        __syncthreads();
        if (tid == 0) {
            int c = above, l = 255;
            for (; l >= 0; l--) {
                if (c + (int)hist[l] >= NCAND) break;
                c += (int)hist[l];
            }
            sL = l; sStrict = c; cA = 0; cT = 0;
        }
        __syncthreads();
        const unsigned int kT = ((unsigned int)B << 8) | (unsigned int)sL;
        const int strict = sStrict;
        for (int i = tid; i < n; i += 256) {
            unsigned int k = list[i] >> 16;
            int idx = (int)(list[i] & 0xFFFFu);
            if (k > kT) {
                int s = atomicAdd(&cA, 1);
                g_cand[row * NCAND + s] = idx;
            } else if (k == kT) {
                int t = atomicAdd(&cT, 1);
                if (strict + t < NCAND)
                    g_cand[row * NCAND + strict + t] = idx;
            }
        }
        return;
    }

    // ---- fallback: full 3-pass histogram over g_pre (biased keys) ----
    const uint4* p4 = (const uint4*)(g_pre + (size_t)row * N_LAT);
    for (int q = tid; q < N_LAT / 8; q += 256) {
        uint4 w = p4[q];
        unsigned int v[4] = {w.x, w.y, w.z, w.w};
#pragma unroll
        for (int j = 0; j < 4; j++) {
            atomicAdd(&hist[bkey(v[j] & 0xFFFFu) >> 8], 1u);
            atomicAdd(&hist[bkey(v[j] >> 16) >> 8], 1u);
        }
    }
    __syncthreads();
    if (tid == 0) {
        int c = 0, b = 255;
        for (; b >= 0; b--) {
            if (c + (int)hist[b] >= NCAND) break;
            c += (int)hist[b];
        }
        sB = b; sAbove = c;
    }
    __syncthreads();
    const int B = sB, above = sAbove;
    hist[tid] = 0u;
    __syncthreads();
    for (int q = tid; q < N_LAT / 8; q += 256) {
        uint4 w = p4[q];
        unsigned int v[4] = {w.x, w.y, w.z, w.w};
#pragma unroll
        for (int j = 0; j < 4; j++) {
            unsigned int k0 = bkey(v[j] & 0xFFFFu);
            unsigned int k1 = bkey(v[j] >> 16);
            if ((int)(k0 >> 8) == B) atomicAdd(&hist[k0 & 255u], 1u);
            if ((int)(k1 >> 8) == B) atomicAdd(&hist[k1 & 255u], 1u);
        }
    }
    __syncthreads();
    if (tid == 0) {
        int c = above, l = 255;
        for (; l >= 0; l--) {
            if (c + (int)hist[l] >= NCAND) break;
            c += (int)hist[l];
        }
        sL = l; sStrict = c; cA = 0; cT = 0;
    }
    __syncthreads();
    const unsigned int kT = ((unsigned int)B << 8) | (unsigned int)sL;
    const int strict = sStrict;
    for (int q = tid; q < N_LAT / 8; q += 256) {
        uint4 w = p4[q];
        unsigned int v[4] = {w.x, w.y, w.z, w.w};
#pragma unroll
        for (int j = 0; j < 4; j++) {
#pragma unroll
            for (int h = 0; h < 2; h++) {
                unsigned int k = bkey(h ? (v[j] >> 16) : (v[j] & 0xFFFFu));
                if (k > kT) {
                    int s = atomicAdd(&cA, 1);
                    g_cand[row * NCAND + s] = q * 8 + j * 2 + h;
                } else if (k == kT) {
                    int t = atomicAdd(&cT, 1);
                    if (strict + t < NCAND)
                        g_cand[row * NCAND + strict + t] = q * 8 + j * 2 + h;
                }
            }
        }
    }
}

// ------------------------- exact fp32 rescore ------------------------------
__global__ __launch_bounds__(192) void k_rescore(const float* __restrict__ x,
                                                 const float* __restrict__ W_enc,
                                                 const float* __restrict__ b_enc,
                                                 const float* __restrict__ b_dec) {
    const int tid = threadIdx.x;
    const int row0 = blockIdx.x * 4;
    __shared__ __align__(16) float sx[4 * D_IN];
    for (int i = tid; i < 4 * D_IN; i += 192) {
        int r = i >> 11, col = i & (D_IN - 1);
        sx[i] = x[(size_t)(row0 + r) * D_IN + col] - b_dec[col];
    }
    __syncthreads();
    const int rl = tid / 48;
    const int ci = tid % 48;
    const int row = row0 + rl;
    const int c = g_cand[row * NCAND + ci];
    const float4* w4 = (const float4*)(W_enc + (size_t)c * D_IN);
    const float4* a4 = (const float4*)(sx + rl * D_IN);
    float s = 0.f;
#pragma unroll 4
    for (int q = 0; q < D_IN / 4; q++) {
        float4 w = w4[q];
        float4 a = a4[q];
        s = fmaf(a.x, w.x, s);
        s = fmaf(a.y, w.y, s);
        s = fmaf(a.z, w.z, s);
        s = fmaf(a.w, w.w, s);
    }
    float v = s + b_enc[c];
    g_cval[row * NCAND + ci] = v > 0.f ? v : 0.f;
}

// ------------------------- exact top-32 select -----------------------------
__global__ void k_select(float* __restrict__ out) {
    const int row = blockIdx.x;
    const int lane = threadIdx.x;
    float v0 = g_cval[row * NCAND + lane];
    int   i0 = g_cand[row * NCAND + lane];
    float v1 = (lane < NCAND - 32) ? g_cval[row * NCAND + 32 + lane] : -1e30f;
    int   i1 = (lane < NCAND - 32) ? g_cand[row * NCAND + 32 + lane] : 0x7FFFFFFF;

    for (int r = 0; r < KSEL; r++) {
        float bv; int bi;
        if (v0 > v1 || (v0 == v1 && i0 < i1)) { bv = v0; bi = i0; }
        else                                   { bv = v1; bi = i1; }
#pragma unroll
        for (int o = 16; o; o >>= 1) {
            float ov = __shfl_xor_sync(0xFFFFFFFFu, bv, o);
            int   oi = __shfl_xor_sync(0xFFFFFFFFu, bi, o);
            if (ov > bv || (ov == bv && oi < bi)) { bv = ov; bi = oi; }
        }
        if (lane == 0) {
            g_tact[row * KSEL + r] = bv;
            g_tidx[row * KSEL + r] = bi;
            out[OFF_ACT + row * KSEL + r] = bv;
            out[OFF_IDX + row * KSEL + r] = (float)bi;
        }
        if (i0 == bi) v0 = -1e30f;
        if (i1 == bi) v1 = -1e30f;
    }
}

// ------------------------- sparse decode + err^2 ---------------------------
__global__ void k_decode(const float* __restrict__ x, const float* __restrict__ W_dec,
                         const float* __restrict__ b_dec, float* __restrict__ out) {
    const int row = blockIdx.x;
    const int tid = threadIdx.x;
    __shared__ float sa[KSEL];
    __shared__ int   si[KSEL];
    __shared__ float red[256];
    if (tid < KSEL) { sa[tid] = g_tact[row * KSEL + tid]; si[tid] = g_tidx[row * KSEL + tid]; }
    __syncthreads();

    const float4* bd4 = (const float4*)b_dec;
    float4 a0 = bd4[tid];
    float4 a1 = bd4[tid + 256];
#pragma unroll 4
    for (int k = 0; k < KSEL; k++) {
        const float4* w4 = (const float4*)(W_dec + (size_t)si[k] * D_IN);
        float a = sa[k];
        float4 w0 = w4[tid], w1 = w4[tid + 256];
        a0.x += a * w0.x; a0.y += a * w0.y; a0.z += a * w0.z; a0.w += a * w0.w;
        a1.x += a * w1.x; a1.y += a * w1.y; a1.z += a * w1.z; a1.w += a * w1.w;
    }
    const float4* x4 = (const float4*)(x + (size_t)row * D_IN);
    float4 x0 = x4[tid], x1 = x4[tid + 256];
    ((float4*)out)[(size_t)row * (D_IN / 4) + tid] = a0;
    ((float4*)out)[(size_t)row * (D_IN / 4) + tid + 256] = a1;
    float e2 = 0.f;
    float d;
    d = x0.x - a0.x; e2 += d * d;  d = x0.y - a0.y; e2 += d * d;
    d = x0.z - a0.z; e2 += d * d;  d = x0.w - a0.w; e2 += d * d;
    d = x1.x - a1.x; e2 += d * d;  d = x1.y - a1.y; e2 += d * d;
    d = x1.z - a1.z; e2 += d * d;  d = x1.w - a1.w; e2 += d * d;

    red[tid] = e2;
    __syncthreads();
    for (int s = 128; s; s >>= 1) {
        if (tid < s) red[tid] += red[tid + s];
        __syncthreads();
    }
    if (tid == 0) atomicAdd(&g_err2, (double)red[0]);
}

// ------------------------- x stats: colsums + sum(x^2) ---------------------
__global__ void k_stats(const float* __restrict__ x) {
    const int b = blockIdx.x;
    const int tid = threadIdx.x;
    const float4* x4 = (const float4*)x;
    float4 a0 = make_float4(0.f, 0.f, 0.f, 0.f), a1 = a0;
    float sq = 0.f;
    for (int r = 0; r < 32; r++) {
        size_t base = (size_t)(b * 32 + r) * (D_IN / 4);
        float4 f0 = x4[base + tid], f1 = x4[base + tid + 256];
        a0.x += f0.x; a0.y += f0.y; a0.z += f0.z; a0.w += f0.w;
        a1.x += f1.x; a1.y += f1.y; a1.z += f1.z; a1.w += f1.w;
        sq += f0.x * f0.x + f0.y * f0.y + f0.z * f0.z + f0.w * f0.w;
        sq += f1.x * f1.x + f1.y * f1.y + f1.z * f1.z + f1.w * f1.w;
    }
    atomicAdd(&g_colsum[tid * 4 + 0], a0.x);
    atomicAdd(&g_colsum[tid * 4 + 1], a0.y);
    atomicAdd(&g_colsum[tid * 4 + 2], a0.z);
    atomicAdd(&g_colsum[tid * 4 + 3], a0.w);
    atomicAdd(&g_colsum[1024 + tid * 4 + 0], a1.x);
    atomicAdd(&g_colsum[1024 + tid * 4 + 1], a1.y);
    atomicAdd(&g_colsum[1024 + tid * 4 + 2], a1.z);
    atomicAdd(&g_colsum[1024 + tid * 4 + 3], a1.w);

    __shared__ float red[256];
    red[tid] = sq;
    __syncthreads();
    for (int s = 128; s; s >>= 1) {
        if (tid < s) red[tid] += red[tid + s];
        __syncthreads();
    }
    if (tid == 0) atomicAdd(&g_sumsq, (double)red[0]);
}

// ------------------------- finalize fvu ------------------------------------
__global__ void k_final(float* __restrict__ out) {
    const int tid = threadIdx.x;
    __shared__ float red[256];
    float s = 0.f;
    for (int c = tid; c < D_IN; c += 256) {
        float v = g_colsum[c];
        s += v * v;
    }
    red[tid] = s;
    __syncthreads();
    for (int q = 128; q; q >>= 1) {
        if (tid < q) red[tid] += red[tid + q];
        __syncthreads();
    }
    if (tid == 0) {
        double tv = g_sumsq - (double)red[0] / (double)B_ROWS;
        double fvu = g_err2 / tv;
        out[OFF_SC + 0] = (float)fvu;
        out[OFF_SC + 1] = 0.f;
        out[OFF_SC + 2] = 0.f;
    }
}

// ------------------------- launch ------------------------------------------
extern "C" void kernel_launch(void* const* d_in, const int* in_sizes, int n_in,
                              void* d_out, int out_size) {
    const float* x     = (const float*)d_in[0];
    const float* W_enc = (const float*)d_in[1];
    const float* b_enc = (const float*)d_in[2];
    const float* W_dec = (const float*)d_in[3];
    const float* b_dec = (const float*)d_in[4];
    float* out = (float*)d_out;

    cudaFuncSetAttribute(k_gemm, cudaFuncAttributeMaxDynamicSharedMemorySize, GEMM_SMEM);

    k_init<<<16, 256>>>();
    k_conv_x<<<(B_ROWS * (D_IN / 4)) / 256, 256>>>(x, b_dec);
    k_conv_w<<<(N_LAT * (D_IN / 4)) / 256, 256>>>(W_enc);
    k_gemm<<<dim3(B_ROWS / BM, N_LAT / BN), 256, GEMM_SMEM>>>(b_enc);
    k_topk<<<B_ROWS, 256>>>();
    k_rescore<<<B_ROWS / 4, 192>>>(x, W_enc, b_enc, b_dec);
    k_select<<<B_ROWS, 32>>>(out);
    k_decode<<<B_ROWS, 256>>>(x, W_dec, b_dec, out);
    k_stats<<<128, 256>>>(x);
    k_final<<<1, 256>>>(out);
}

// round 14
// speedup vs baseline: 1.0179x; 1.0179x over previous
#include <cuda_runtime.h>
#include <cuda_bf16.h>
#include <cstdint>

// ---------------------------------------------------------------------------
// SparseCoder (TopK SAE) forward, GB300 sm_103a
// Round 14: R13 + g_cnt padded to one counter per 128B cache line
// (g_cnt[row<<5]). R13's GEMM regression was LTS-slice serialization of ~3M
// atomics funneled into the 4 cache lines of a dense 16KB counter array;
// padding spreads them across all L2 slices. Everything else unchanged.
// ---------------------------------------------------------------------------

#define B_ROWS 4096
#define D_IN   2048
#define N_LAT  32768
#define KSEL   32
#define NCAND  48
#define LCAP   2048
#define CSTR   32      // g_cnt stride in ints (128 B = one L2 line per row)

#define OFF_ACT  (B_ROWS * D_IN)
#define OFF_IDX  (OFF_ACT + B_ROWS * KSEL)
#define OFF_SC   (OFF_IDX + B_ROWS * KSEL)

// ------------------------- device scratch ----------------------------------
__device__ __nv_bfloat16 g_xb16[(size_t)B_ROWS * D_IN];     // 16 MB
__device__ __nv_bfloat16 g_wb16[(size_t)N_LAT * D_IN];      // 128 MB
__device__ __nv_bfloat16 g_pre [(size_t)B_ROWS * N_LAT];    // 256 MB
__device__ unsigned g_list[(size_t)B_ROWS * LCAP];          // 32 MB
__device__ int    g_cnt [B_ROWS * CSTR];                    // 512 KB (padded)
__device__ int    g_cand[B_ROWS * NCAND];
__device__ float  g_cval[B_ROWS * NCAND];
__device__ int    g_tidx[B_ROWS * KSEL];
__device__ float  g_tact[B_ROWS * KSEL];
__device__ float  g_colsum[D_IN];
__device__ double g_err2;
__device__ double g_sumsq;

// ------------------------- init --------------------------------------------
__global__ void k_init() {
    int i = blockIdx.x * blockDim.x + threadIdx.x;
    if (i < D_IN) g_colsum[i] = 0.f;
    if (i < B_ROWS) g_cnt[i << 5] = 0;
    if (i == 0) { g_err2 = 0.0; g_sumsq = 0.0; }
}

// ------------------------- bf16 conversions --------------------------------
__global__ void k_conv_x(const float* __restrict__ x, const float* __restrict__ b_dec) {
    int i4 = blockIdx.x * blockDim.x + threadIdx.x;
    if (i4 >= B_ROWS * (D_IN / 4)) return;
    int c4 = i4 & (D_IN / 4 - 1);
    float4 v = ((const float4*)x)[i4];
    float4 b = ((const float4*)b_dec)[c4];
    __nv_bfloat162 lo = __floats2bfloat162_rn(v.x - b.x, v.y - b.y);
    __nv_bfloat162 hi = __floats2bfloat162_rn(v.z - b.z, v.w - b.w);
    uint2 u;
    u.x = *(unsigned int*)&lo;
    u.y = *(unsigned int*)&hi;
    ((uint2*)g_xb16)[i4] = u;
}

__global__ void k_conv_w(const float* __restrict__ W) {
    int i4 = blockIdx.x * blockDim.x + threadIdx.x;
    if (i4 >= N_LAT * (D_IN / 4)) return;
    float4 v = ((const float4*)W)[i4];
    __nv_bfloat162 lo = __floats2bfloat162_rn(v.x, v.y);
    __nv_bfloat162 hi = __floats2bfloat162_rn(v.z, v.w);
    uint2 u;
    u.x = *(unsigned int*)&lo;
    u.y = *(unsigned int*)&hi;
    ((uint2*)g_wb16)[i4] = u;
}

// ------------------------- screening GEMM (mma.sync, pipelined) ------------
#define BM 128
#define BN 256
#define BK 128
#define NSTG 2
#define NT (D_IN / BK)            // 16 k-tiles
#define SP 136                    // smem row stride in bf16 (272 B, conflict-free ldmatrix)
#define AS_ELE (BM * SP)          // 17408
#define BS_ELE (BN * SP)          // 34816
#define STG_ELE (AS_ELE + BS_ELE) // 52224 elems = 104448 B
#define GEMM_SMEM (NSTG * STG_ELE * 2)   // 208896 B

__device__ __forceinline__ void ldsm4(unsigned int* r, const void* p) {
    unsigned int a = (unsigned int)__cvta_generic_to_shared(p);
    asm volatile("ldmatrix.sync.aligned.m8n8.x4.shared.b16 {%0,%1,%2,%3}, [%4];"
                 : "=r"(r[0]), "=r"(r[1]), "=r"(r[2]), "=r"(r[3]) : "r"(a));
}

__device__ __forceinline__ void mma16816(float* d, const unsigned int* a, const unsigned int* b) {
    asm volatile("mma.sync.aligned.m16n8k16.row.col.f32.bf16.bf16.f32 "
                 "{%0,%1,%2,%3},{%4,%5,%6,%7},{%8,%9},{%0,%1,%2,%3};"
                 : "+f"(d[0]), "+f"(d[1]), "+f"(d[2]), "+f"(d[3])
                 : "r"(a[0]), "r"(a[1]), "r"(a[2]), "r"(a[3]), "r"(b[0]), "r"(b[1]));
}

__device__ __forceinline__ void cp16(void* dst, const void* src) {
    unsigned int d = (unsigned int)__cvta_generic_to_shared(dst);
    asm volatile("cp.async.cg.shared.global [%0], [%1], 16;" :: "r"(d), "l"(src) : "memory");
}
#define CP_COMMIT() asm volatile("cp.async.commit_group;" ::: "memory")
#define CP_WAIT0()  asm volatile("cp.async.wait_group 0;" ::: "memory")

__global__ __launch_bounds__(256, 1) void k_gemm(const float* __restrict__ b_enc) {
    extern __shared__ __align__(16) __nv_bfloat16 smem[];   // [NSTG][STG_ELE]
    const int m0 = blockIdx.x * BM;       // 32 m-blocks (fast dim)
    const int n0 = blockIdx.y * BN;       // 128 n-blocks
    const int tid = threadIdx.x;
    const int lane = tid & 31, wid = tid >> 5;
    const int wm = (wid & 1) << 6;        // warp row offset (2 warps in m, 64 each)
    const int wn = (wid >> 1) << 6;       // warp col offset (4 warps in n, 64 each)

    float acc[4][8][4];
#pragma unroll
    for (int i = 0; i < 4; i++)
#pragma unroll
        for (int j = 0; j < 8; j++)
#pragma unroll
            for (int q = 0; q < 4; q++) acc[i][j][q] = 0.f;

    // stage loader: 6144 chunks of 16B (A: 2048, B: 4096), 24 per thread
    auto load_stage = [&](int kt, int stg) {
        __nv_bfloat16* s = smem + stg * STG_ELE;
        const int k0 = kt * BK;
#pragma unroll
        for (int i = 0; i < 24; i++) {
            int c = tid + i * 256;
            if (c < 2048) {
                int r = c >> 4, q = c & 15;
                cp16(s + r * SP + q * 8,
                     g_xb16 + (size_t)(m0 + r) * D_IN + k0 + q * 8);
            } else {
                int j = c - 2048;
                int r = j >> 4, q = j & 15;
                cp16(s + AS_ELE + r * SP + q * 8,
                     g_wb16 + (size_t)(n0 + r) * D_IN + k0 + q * 8);
            }
        }
        CP_COMMIT();
    };

    load_stage(0, 0);

    const int rowA = (lane & 15);
    const int colA = (lane >> 4) << 3;
    const int rowB = ((lane >> 4) << 3) + (lane & 7);
    const int colB = ((lane >> 3) & 1) << 3;

    for (int kt = 0; kt < NT; kt++) {
        // tile kt's cp.asyncs (issued one full tile ago) complete
        CP_WAIT0();
        // publish them to all threads; also proves every warp finished
        // computing tile kt-1 -> stage (kt+1)&1 is free to overwrite
        __syncthreads();
        if (kt + 1 < NT) load_stage(kt + 1, (kt + 1) & 1);

        const __nv_bfloat16* sA = smem + (kt & 1) * STG_ELE;
        const __nv_bfloat16* sB = sA + AS_ELE;

        unsigned int af[2][4][4], bfr[2][4][4];
#pragma unroll
        for (int mf = 0; mf < 4; mf++)
            ldsm4(af[0][mf], &sA[(wm + mf * 16 + rowA) * SP + colA]);
#pragma unroll
        for (int pr = 0; pr < 4; pr++)
            ldsm4(bfr[0][pr], &sB[(wn + pr * 16 + rowB) * SP + colB]);

#pragma unroll
        for (int s = 0; s < 8; s++) {
            const int cur = s & 1;
            if (s < 7) {
                const int nb = (s + 1) & 1;
                const int kk = (s + 1) * 16;
#pragma unroll
                for (int mf = 0; mf < 4; mf++)
                    ldsm4(af[nb][mf], &sA[(wm + mf * 16 + rowA) * SP + kk + colA]);
#pragma unroll
                for (int pr = 0; pr < 4; pr++)
                    ldsm4(bfr[nb][pr], &sB[(wn + pr * 16 + rowB) * SP + kk + colB]);
            }
#pragma unroll
            for (int mf = 0; mf < 4; mf++)
#pragma unroll
                for (int nf = 0; nf < 8; nf++)
                    mma16816(acc[mf][nf], af[cur][mf], &bfr[cur][nf >> 1][(nf & 1) * 2]);
        }
    }

    // epilogue: + b_enc, relu, bf16 store to g_pre + candidate extraction
#pragma unroll
    for (int mf = 0; mf < 4; mf++) {
        int r0 = m0 + wm + mf * 16 + (lane >> 2);
#pragma unroll
        for (int nf = 0; nf < 8; nf++) {
            int c0 = n0 + wn + nf * 8 + ((lane & 3) << 1);
            float2 be = *(const float2*)(b_enc + c0);
            float v0 = acc[mf][nf][0] + be.x; v0 = v0 > 0.f ? v0 : 0.f;
            float v1 = acc[mf][nf][1] + be.y; v1 = v1 > 0.f ? v1 : 0.f;
            float v2 = acc[mf][nf][2] + be.x; v2 = v2 > 0.f ? v2 : 0.f;
            float v3 = acc[mf][nf][3] + be.y; v3 = v3 > 0.f ? v3 : 0.f;
            __nv_bfloat162 p0 = __floats2bfloat162_rn(v0, v1);
            __nv_bfloat162 p1 = __floats2bfloat162_rn(v2, v3);
            *(__nv_bfloat162*)&g_pre[(size_t)r0 * N_LAT + c0] = p0;
            *(__nv_bfloat162*)&g_pre[(size_t)(r0 + 8) * N_LAT + c0] = p1;
            unsigned pu0 = *(unsigned*)&p0;   // lo = bf16(v0), hi = bf16(v1)
            unsigned pu1 = *(unsigned*)&p1;   // lo = bf16(v2), hi = bf16(v3)
            if (v0 >= 2.0f) {
                int p = atomicAdd(&g_cnt[r0 << 5], 1);
                if (p < LCAP) g_list[(size_t)r0 * LCAP + p] = (pu0 << 16) | (unsigned)c0;
            }
            if (v1 >= 2.0f) {
                int p = atomicAdd(&g_cnt[r0 << 5], 1);
                if (p < LCAP) g_list[(size_t)r0 * LCAP + p] = (pu0 & 0xFFFF0000u) | (unsigned)(c0 + 1);
            }
            if (v2 >= 2.0f) {
                int p = atomicAdd(&g_cnt[(r0 + 8) << 5], 1);
                if (p < LCAP) g_list[(size_t)(r0 + 8) * LCAP + p] = (pu1 << 16) | (unsigned)c0;
            }
            if (v3 >= 2.0f) {
                int p = atomicAdd(&g_cnt[(r0 + 8) << 5], 1);
                if (p < LCAP) g_list[(size_t)(r0 + 8) * LCAP + p] = (pu1 & 0xFFFF0000u) | (unsigned)(c0 + 1);
            }
        }
    }
}

// ------------------------- top-48 candidates -------------------------------
__device__ __forceinline__ unsigned int bkey(unsigned int u) {
    return (u & 0x8000u) ? (u ^ 0xFFFFu) : (u ^ 0x8000u);
}

__global__ void k_topk(void) {
    const int row = blockIdx.x;
    const int tid = threadIdx.x;          // 256
    __shared__ unsigned int list[LCAP];
    __shared__ unsigned int hist[256];
    __shared__ int sB, sAbove, sL, sStrict, cA, cT;

    const int n = g_cnt[row << 5];
    hist[tid] = 0u;
    __syncthreads();

    if (n >= NCAND && n <= LCAP) {
        // ---- fast path: short-list radix select from g_list ----
        const unsigned* gl = g_list + (size_t)row * LCAP;
        for (int i = tid; i < n; i += 256) {
            unsigned e = gl[i];
            list[i] = e;
            atomicAdd(&hist[e >> 24], 1u);
        }
        __syncthreads();
        if (tid == 0) {
            int c = 0, b = 255;
            for (; b >= 0; b--) {
                if (c + (int)hist[b] >= NCAND) break;
                c += (int)hist[b];
            }
            sB = b; sAbove = c;
        }
        __syncthreads();
        const int B = sB, above = sAbove;
        hist[tid] = 0u;
        __syncthreads();
        for (int i = tid; i < n; i += 256) {
            unsigned int k = list[i] >> 16;
            if ((int)(k >> 8) == B) atomicAdd(&hist[k & 255u], 1u);
        }
        __syncthreads();
        if (tid == 0) {
            int c = above, l = 255;
            for (; l >= 0; l--) {
                if (c + (int)hist[l] >= NCAND) break;
                c += (int)hist[l];
            }
            sL = l; sStrict = c; cA = 0; cT = 0;
        }
        __syncthreads();
        const unsigned int kT = ((unsigned int)B << 8) | (unsigned int)sL;
        const int strict = sStrict;
        for (int i = tid; i < n; i += 256) {
            unsigned int k = list[i] >> 16;
            int idx = (int)(list[i] & 0xFFFFu);
            if (k > kT) {
                int s = atomicAdd(&cA, 1);
                g_cand[row * NCAND + s] = idx;
            } else if (k == kT) {
                int t = atomicAdd(&cT, 1);
                if (strict + t < NCAND)
                    g_cand[row * NCAND + strict + t] = idx;
            }
        }
        return;
    }

    // ---- fallback: full 3-pass histogram over g_pre (biased keys) ----
    const uint4* p4 = (const uint4*)(g_pre + (size_t)row * N_LAT);
    for (int q = tid; q < N_LAT / 8; q += 256) {
        uint4 w = p4[q];
        unsigned int v[4] = {w.x, w.y, w.z, w.w};
#pragma unroll
        for (int j = 0; j < 4; j++) {
            atomicAdd(&hist[bkey(v[j] & 0xFFFFu) >> 8], 1u);
            atomicAdd(&hist[bkey(v[j] >> 16) >> 8], 1u);
        }
    }
    __syncthreads();
    if (tid == 0) {
        int c = 0, b = 255;
        for (; b >= 0; b--) {
            if (c + (int)hist[b] >= NCAND) break;
            c += (int)hist[b];
        }
        sB = b; sAbove = c;
    }
    __syncthreads();
    const int B = sB, above = sAbove;
    hist[tid] = 0u;
    __syncthreads();
    for (int q = tid; q < N_LAT / 8; q += 256) {
        uint4 w = p4[q];
        unsigned int v[4] = {w.x, w.y, w.z, w.w};
#pragma unroll
        for (int j = 0; j < 4; j++) {
            unsigned int k0 = bkey(v[j] & 0xFFFFu);
            unsigned int k1 = bkey(v[j] >> 16);
            if ((int)(k0 >> 8) == B) atomicAdd(&hist[k0 & 255u], 1u);
            if ((int)(k1 >> 8) == B) atomicAdd(&hist[k1 & 255u], 1u);
        }
    }
    __syncthreads();
    if (tid == 0) {
        int c = above, l = 255;
        for (; l >= 0; l--) {
            if (c + (int)hist[l] >= NCAND) break;
            c += (int)hist[l];
        }
        sL = l; sStrict = c; cA = 0; cT = 0;
    }
    __syncthreads();
    const unsigned int kT = ((unsigned int)B << 8) | (unsigned int)sL;
    const int strict = sStrict;
    for (int q = tid; q < N_LAT / 8; q += 256) {
        uint4 w = p4[q];
        unsigned int v[4] = {w.x, w.y, w.z, w.w};
#pragma unroll
        for (int j = 0; j < 4; j++) {
#pragma unroll
            for (int h = 0; h < 2; h++) {
                unsigned int k = bkey(h ? (v[j] >> 16) : (v[j] & 0xFFFFu));
                if (k > kT) {
                    int s = atomicAdd(&cA, 1);
                    g_cand[row * NCAND + s] = q * 8 + j * 2 + h;
                } else if (k == kT) {
                    int t = atomicAdd(&cT, 1);
                    if (strict + t < NCAND)
                        g_cand[row * NCAND + strict + t] = q * 8 + j * 2 + h;
                }
            }
        }
    }
}

// ------------------------- exact fp32 rescore ------------------------------
__global__ __launch_bounds__(192) void k_rescore(const float* __restrict__ x,
                                                 const float* __restrict__ W_enc,
                                                 const float* __restrict__ b_enc,
                                                 const float* __restrict__ b_dec) {
    const int tid = threadIdx.x;
    const int row0 = blockIdx.x * 4;
    __shared__ __align__(16) float sx[4 * D_IN];
    for (int i = tid; i < 4 * D_IN; i += 192) {
        int r = i >> 11, col = i & (D_IN - 1);
        sx[i] = x[(size_t)(row0 + r) * D_IN + col] - b_dec[col];
    }
    __syncthreads();
    const int rl = tid / 48;
    const int ci = tid % 48;
    const int row = row0 + rl;
    const int c = g_cand[row * NCAND + ci];
    const float4* w4 = (const float4*)(W_enc + (size_t)c * D_IN);
    const float4* a4 = (const float4*)(sx + rl * D_IN);
    float s = 0.f;
#pragma unroll 4
    for (int q = 0; q < D_IN / 4; q++) {
        float4 w = w4[q];
        float4 a = a4[q];
        s = fmaf(a.x, w.x, s);
        s = fmaf(a.y, w.y, s);
        s = fmaf(a.z, w.z, s);
        s = fmaf(a.w, w.w, s);
    }
    float v = s + b_enc[c];
    g_cval[row * NCAND + ci] = v > 0.f ? v : 0.f;
}

// ------------------------- exact top-32 select -----------------------------
__global__ void k_select(float* __restrict__ out) {
    const int row = blockIdx.x;
    const int lane = threadIdx.x;
    float v0 = g_cval[row * NCAND + lane];
    int   i0 = g_cand[row * NCAND + lane];
    float v1 = (lane < NCAND - 32) ? g_cval[row * NCAND + 32 + lane] : -1e30f;
    int   i1 = (lane < NCAND - 32) ? g_cand[row * NCAND + 32 + lane] : 0x7FFFFFFF;

    for (int r = 0; r < KSEL; r++) {
        float bv; int bi;
        if (v0 > v1 || (v0 == v1 && i0 < i1)) { bv = v0; bi = i0; }
        else                                   { bv = v1; bi = i1; }
#pragma unroll
        for (int o = 16; o; o >>= 1) {
            float ov = __shfl_xor_sync(0xFFFFFFFFu, bv, o);
            int   oi = __shfl_xor_sync(0xFFFFFFFFu, bi, o);
            if (ov > bv || (ov == bv && oi < bi)) { bv = ov; bi = oi; }
        }
        if (lane == 0) {
            g_tact[row * KSEL + r] = bv;
            g_tidx[row * KSEL + r] = bi;
            out[OFF_ACT + row * KSEL + r] = bv;
            out[OFF_IDX + row * KSEL + r] = (float)bi;
        }
        if (i0 == bi) v0 = -1e30f;
        if (i1 == bi) v1 = -1e30f;
    }
}

// ------------------------- sparse decode + err^2 ---------------------------
__global__ void k_decode(const float* __restrict__ x, const float* __restrict__ W_dec,
                         const float* __restrict__ b_dec, float* __restrict__ out) {
    const int row = blockIdx.x;
    const int tid = threadIdx.x;
    __shared__ float sa[KSEL];
    __shared__ int   si[KSEL];
    __shared__ float red[256];
    if (tid < KSEL) { sa[tid] = g_tact[row * KSEL + tid]; si[tid] = g_tidx[row * KSEL + tid]; }
    __syncthreads();

    const float4* bd4 = (const float4*)b_dec;
    float4 a0 = bd4[tid];
    float4 a1 = bd4[tid + 256];
#pragma unroll 4
    for (int k = 0; k < KSEL; k++) {
        const float4* w4 = (const float4*)(W_dec + (size_t)si[k] * D_IN);
        float a = sa[k];
        float4 w0 = w4[tid], w1 = w4[tid + 256];
        a0.x += a * w0.x; a0.y += a * w0.y; a0.z += a * w0.z; a0.w += a * w0.w;
        a1.x += a * w1.x; a1.y += a * w1.y; a1.z += a * w1.z; a1.w += a * w1.w;
    }
    const float4* x4 = (const float4*)(x + (size_t)row * D_IN);
    float4 x0 = x4[tid], x1 = x4[tid + 256];
    ((float4*)out)[(size_t)row * (D_IN / 4) + tid] = a0;
    ((float4*)out)[(size_t)row * (D_IN / 4) + tid + 256] = a1;
    float e2 = 0.f;
    float d;
    d = x0.x - a0.x; e2 += d * d;  d = x0.y - a0.y; e2 += d * d;
    d = x0.z - a0.z; e2 += d * d;  d = x0.w - a0.w; e2 += d * d;
    d = x1.x - a1.x; e2 += d * d;  d = x1.y - a1.y; e2 += d * d;
    d = x1.z - a1.z; e2 += d * d;  d = x1.w - a1.w; e2 += d * d;

    red[tid] = e2;
    __syncthreads();
    for (int s = 128; s; s >>= 1) {
        if (tid < s) red[tid] += red[tid + s];
        __syncthreads();
    }
    if (tid == 0) atomicAdd(&g_err2, (double)red[0]);
}

// ------------------------- x stats: colsums + sum(x^2) ---------------------
__global__ void k_stats(const float* __restrict__ x) {
    const int b = blockIdx.x;
    const int tid = threadIdx.x;
    const float4* x4 = (const float4*)x;
    float4 a0 = make_float4(0.f, 0.f, 0.f, 0.f), a1 = a0;
    float sq = 0.f;
    for (int r = 0; r < 32; r++) {
        size_t base = (size_t)(b * 32 + r) * (D_IN / 4);
        float4 f0 = x4[base + tid], f1 = x4[base + tid + 256];
        a0.x += f0.x; a0.y += f0.y; a0.z += f0.z; a0.w += f0.w;
        a1.x += f1.x; a1.y += f1.y; a1.z += f1.z; a1.w += f1.w;
        sq += f0.x * f0.x + f0.y * f0.y + f0.z * f0.z + f0.w * f0.w;
        sq += f1.x * f1.x + f1.y * f1.y + f1.z * f1.z + f1.w * f1.w;
    }
    atomicAdd(&g_colsum[tid * 4 + 0], a0.x);
    atomicAdd(&g_colsum[tid * 4 + 1], a0.y);
    atomicAdd(&g_colsum[tid * 4 + 2], a0.z);
    atomicAdd(&g_colsum[tid * 4 + 3], a0.w);
    atomicAdd(&g_colsum[1024 + tid * 4 + 0], a1.x);
    atomicAdd(&g_colsum[1024 + tid * 4 + 1], a1.y);
    atomicAdd(&g_colsum[1024 + tid * 4 + 2], a1.z);
    atomicAdd(&g_colsum[1024 + tid * 4 + 3], a1.w);

    __shared__ float red[256];
    red[tid] = sq;
    __syncthreads();
    for (int s = 128; s; s >>= 1) {
        if (tid < s) red[tid] += red[tid + s];
        __syncthreads();
    }
    if (tid == 0) atomicAdd(&g_sumsq, (double)red[0]);
}

// ------------------------- finalize fvu ------------------------------------
__global__ void k_final(float* __restrict__ out) {
    const int tid = threadIdx.x;
    __shared__ float red[256];
    float s = 0.f;
    for (int c = tid; c < D_IN; c += 256) {
        float v = g_colsum[c];
        s += v * v;
    }
    red[tid] = s;
    __syncthreads();
    for (int q = 128; q; q >>= 1) {
        if (tid < q) red[tid] += red[tid + q];
        __syncthreads();
    }
    if (tid == 0) {
        double tv = g_sumsq - (double)red[0] / (double)B_ROWS;
        double fvu = g_err2 / tv;
        out[OFF_SC + 0] = (float)fvu;
        out[OFF_SC + 1] = 0.f;
        out[OFF_SC + 2] = 0.f;
    }
}

// ------------------------- launch ------------------------------------------
extern "C" void kernel_launch(void* const* d_in, const int* in_sizes, int n_in,
                              void* d_out, int out_size) {
    const float* x     = (const float*)d_in[0];
    const float* W_enc = (const float*)d_in[1];
    const float* b_enc = (const float*)d_in[2];
    const float* W_dec = (const float*)d_in[3];
    const float* b_dec = (const float*)d_in[4];
    float* out = (float*)d_out;

    cudaFuncSetAttribute(k_gemm, cudaFuncAttributeMaxDynamicSharedMemorySize, GEMM_SMEM);

    k_init<<<16, 256>>>();
    k_conv_x<<<(B_ROWS * (D_IN / 4)) / 256, 256>>>(x, b_dec);
    k_conv_w<<<(N_LAT * (D_IN / 4)) / 256, 256>>>(W_enc);
    k_gemm<<<dim3(B_ROWS / BM, N_LAT / BN), 256, GEMM_SMEM>>>(b_enc);
    k_topk<<<B_ROWS, 256>>>();
    k_rescore<<<B_ROWS / 4, 192>>>(x, W_enc, b_enc, b_dec);
    k_select<<<B_ROWS, 32>>>(out);
    k_decode<<<B_ROWS, 256>>>(x, W_dec, b_dec, out);
    k_stats<<<128, 256>>>(x);
    k_final<<<1, 256>>>(out);
}

// round 16
// speedup vs baseline: 1.2942x; 1.2714x over previous
#include <cuda_runtime.h>
#include <cuda_bf16.h>
#include <cstdint>

// ---------------------------------------------------------------------------
// SparseCoder (TopK SAE) forward, GB300 sm_103a
// Round 15: drop epilogue extraction (R13/14 showed it costs ~550us in CTA
// tails). GEMM reconfigured for 2 CTAs/SM: BM=128/BN=128/BK=64/NSTG=3,
// 128 threads (4 warps, 64x64 warp tiles), 110.6KB smem/CTA. Co-resident CTA
// fills barrier/ldsm bubbles. topk = R10's verified threshold scan.
// ---------------------------------------------------------------------------

#define B_ROWS 4096
#define D_IN   2048
#define N_LAT  32768
#define KSEL   32
#define NCAND  48

#define OFF_ACT  (B_ROWS * D_IN)
#define OFF_IDX  (OFF_ACT + B_ROWS * KSEL)
#define OFF_SC   (OFF_IDX + B_ROWS * KSEL)

// ------------------------- device scratch ----------------------------------
__device__ __nv_bfloat16 g_xb16[(size_t)B_ROWS * D_IN];     // 16 MB
__device__ __nv_bfloat16 g_wb16[(size_t)N_LAT * D_IN];      // 128 MB
__device__ __nv_bfloat16 g_pre [(size_t)B_ROWS * N_LAT];    // 256 MB
__device__ int    g_cand[B_ROWS * NCAND];
__device__ float  g_cval[B_ROWS * NCAND];
__device__ int    g_tidx[B_ROWS * KSEL];
__device__ float  g_tact[B_ROWS * KSEL];
__device__ float  g_colsum[D_IN];
__device__ double g_err2;
__device__ double g_sumsq;

// ------------------------- init --------------------------------------------
__global__ void k_init() {
    int i = blockIdx.x * blockDim.x + threadIdx.x;
    if (i < D_IN) g_colsum[i] = 0.f;
    if (i == 0) { g_err2 = 0.0; g_sumsq = 0.0; }
}

// ------------------------- bf16 conversions --------------------------------
__global__ void k_conv_x(const float* __restrict__ x, const float* __restrict__ b_dec) {
    int i4 = blockIdx.x * blockDim.x + threadIdx.x;
    if (i4 >= B_ROWS * (D_IN / 4)) return;
    int c4 = i4 & (D_IN / 4 - 1);
    float4 v = ((const float4*)x)[i4];
    float4 b = ((const float4*)b_dec)[c4];
    __nv_bfloat162 lo = __floats2bfloat162_rn(v.x - b.x, v.y - b.y);
    __nv_bfloat162 hi = __floats2bfloat162_rn(v.z - b.z, v.w - b.w);
    uint2 u;
    u.x = *(unsigned int*)&lo;
    u.y = *(unsigned int*)&hi;
    ((uint2*)g_xb16)[i4] = u;
}

__global__ void k_conv_w(const float* __restrict__ W) {
    int i4 = blockIdx.x * blockDim.x + threadIdx.x;
    if (i4 >= N_LAT * (D_IN / 4)) return;
    float4 v = ((const float4*)W)[i4];
    __nv_bfloat162 lo = __floats2bfloat162_rn(v.x, v.y);
    __nv_bfloat162 hi = __floats2bfloat162_rn(v.z, v.w);
    uint2 u;
    u.x = *(unsigned int*)&lo;
    u.y = *(unsigned int*)&hi;
    ((uint2*)g_wb16)[i4] = u;
}

// ------------------------- screening GEMM (mma.sync, 2 CTA/SM) -------------
#define BM 128
#define BN 128
#define BK 64
#define NSTG 3
#define NT (D_IN / BK)            // 32 k-tiles
#define SP 72                     // smem row stride in bf16 (144 B, conflict-free ldmatrix)
#define AS_ELE (BM * SP)          // 9216
#define BS_ELE (BN * SP)          // 9216
#define STG_ELE (AS_ELE + BS_ELE) // 18432 elems = 36864 B
#define GEMM_SMEM (NSTG * STG_ELE * 2)   // 110592 B -> 2 CTAs/SM

__device__ __forceinline__ void ldsm4(unsigned int* r, const void* p) {
    unsigned int a = (unsigned int)__cvta_generic_to_shared(p);
    asm volatile("ldmatrix.sync.aligned.m8n8.x4.shared.b16 {%0,%1,%2,%3}, [%4];"
                 : "=r"(r[0]), "=r"(r[1]), "=r"(r[2]), "=r"(r[3]) : "r"(a));
}

__device__ __forceinline__ void mma16816(float* d, const unsigned int* a, const unsigned int* b) {
    asm volatile("mma.sync.aligned.m16n8k16.row.col.f32.bf16.bf16.f32 "
                 "{%0,%1,%2,%3},{%4,%5,%6,%7},{%8,%9},{%0,%1,%2,%3};"
                 : "+f"(d[0]), "+f"(d[1]), "+f"(d[2]), "+f"(d[3])
                 : "r"(a[0]), "r"(a[1]), "r"(a[2]), "r"(a[3]), "r"(b[0]), "r"(b[1]));
}

__device__ __forceinline__ void cp16(void* dst, const void* src) {
    unsigned int d = (unsigned int)__cvta_generic_to_shared(dst);
    asm volatile("cp.async.cg.shared.global [%0], [%1], 16;" :: "r"(d), "l"(src) : "memory");
}
#define CP_COMMIT() asm volatile("cp.async.commit_group;" ::: "memory")
#define CP_WAIT1()  asm volatile("cp.async.wait_group 1;" ::: "memory")
#define CP_WAIT0()  asm volatile("cp.async.wait_group 0;" ::: "memory")

__global__ __launch_bounds__(128, 2) void k_gemm(const float* __restrict__ b_enc) {
    extern __shared__ __align__(16) __nv_bfloat16 smem[];   // [NSTG][STG_ELE]
    const int m0 = blockIdx.x * BM;       // 32 m-blocks (fast dim)
    const int n0 = blockIdx.y * BN;       // 256 n-blocks
    const int tid = threadIdx.x;          // 128
    const int lane = tid & 31, wid = tid >> 5;
    const int wm = (wid & 1) << 6;        // 2 warps in m, 64 each
    const int wn = (wid >> 1) << 6;       // 2 warps in n, 64 each

    float acc[4][8][4];
#pragma unroll
    for (int i = 0; i < 4; i++)
#pragma unroll
        for (int j = 0; j < 8; j++)
#pragma unroll
            for (int q = 0; q < 4; q++) acc[i][j][q] = 0.f;

    // stage loader: 2048 chunks of 16B (A: 1024, B: 1024), 16 per thread
    auto load_stage = [&](int kt, int stg) {
        __nv_bfloat16* s = smem + stg * STG_ELE;
        const int k0 = kt * BK;
#pragma unroll
        for (int i = 0; i < 16; i++) {
            int c = tid + i * 128;
            if (c < 1024) {
                int r = c >> 3, q = c & 7;
                cp16(s + r * SP + q * 8,
                     g_xb16 + (size_t)(m0 + r) * D_IN + k0 + q * 8);
            } else {
                int j = c - 1024;
                int r = j >> 3, q = j & 7;
                cp16(s + AS_ELE + r * SP + q * 8,
                     g_wb16 + (size_t)(n0 + r) * D_IN + k0 + q * 8);
            }
        }
        CP_COMMIT();
    };

    load_stage(0, 0);
    load_stage(1, 1);

    const int rowA = (lane & 15);
    const int colA = (lane >> 4) << 3;
    const int rowB = ((lane >> 4) << 3) + (lane & 7);
    const int colB = ((lane >> 3) & 1) << 3;

    for (int kt = 0; kt < NT; kt++) {
        if (kt < NT - 2) { CP_WAIT1(); } else { CP_WAIT0(); }
        // barrier: publishes tile kt copies; proves stage (kt+2)%NSTG free
        __syncthreads();
        if (kt + 2 < NT) load_stage(kt + 2, (kt + 2) % NSTG);

        const __nv_bfloat16* sA = smem + (kt % NSTG) * STG_ELE;
        const __nv_bfloat16* sB = sA + AS_ELE;

        unsigned int af[2][4][4], bfr[2][4][4];
#pragma unroll
        for (int mf = 0; mf < 4; mf++)
            ldsm4(af[0][mf], &sA[(wm + mf * 16 + rowA) * SP + colA]);
#pragma unroll
        for (int pr = 0; pr < 4; pr++)
            ldsm4(bfr[0][pr], &sB[(wn + pr * 16 + rowB) * SP + colB]);

#pragma unroll
        for (int s = 0; s < 4; s++) {
            const int cur = s & 1;
            if (s < 3) {
                const int nb = (s + 1) & 1;
                const int kk = (s + 1) * 16;
#pragma unroll
                for (int mf = 0; mf < 4; mf++)
                    ldsm4(af[nb][mf], &sA[(wm + mf * 16 + rowA) * SP + kk + colA]);
#pragma unroll
                for (int pr = 0; pr < 4; pr++)
                    ldsm4(bfr[nb][pr], &sB[(wn + pr * 16 + rowB) * SP + kk + colB]);
            }
#pragma unroll
            for (int mf = 0; mf < 4; mf++)
#pragma unroll
                for (int nf = 0; nf < 8; nf++)
                    mma16816(acc[mf][nf], af[cur][mf], &bfr[cur][nf >> 1][(nf & 1) * 2]);
        }
    }

    // epilogue: + b_enc, relu, bf16 store
#pragma unroll
    for (int mf = 0; mf < 4; mf++) {
        int r0 = m0 + wm + mf * 16 + (lane >> 2);
#pragma unroll
        for (int nf = 0; nf < 8; nf++) {
            int c0 = n0 + wn + nf * 8 + ((lane & 3) << 1);
            float2 be = *(const float2*)(b_enc + c0);
            float v0 = acc[mf][nf][0] + be.x; v0 = v0 > 0.f ? v0 : 0.f;
            float v1 = acc[mf][nf][1] + be.y; v1 = v1 > 0.f ? v1 : 0.f;
            float v2 = acc[mf][nf][2] + be.x; v2 = v2 > 0.f ? v2 : 0.f;
            float v3 = acc[mf][nf][3] + be.y; v3 = v3 > 0.f ? v3 : 0.f;
            __nv_bfloat162 p0 = __floats2bfloat162_rn(v0, v1);
            __nv_bfloat162 p1 = __floats2bfloat162_rn(v2, v3);
            *(__nv_bfloat162*)&g_pre[(size_t)r0 * N_LAT + c0] = p0;
            *(__nv_bfloat162*)&g_pre[(size_t)(r0 + 8) * N_LAT + c0] = p1;
        }
    }
}

// ------------------------- top-48 candidates -------------------------------
// Fast path: collect values >= 2.0 (bf16 bits >= 0x4000; rank-48 of ~N(0,1)
// is ~2.97, enormous margin) into a short smem list, radix-select top-48.
// Guarded fallback to full 3-pass histogram if list <NCAND or overflowed.
__device__ __forceinline__ unsigned int bkey(unsigned int u) {
    return (u & 0x8000u) ? (u ^ 0xFFFFu) : (u ^ 0x8000u);
}

#define TK_CAP 4096

__global__ void k_topk(void) {
    const int row = blockIdx.x;
    const int tid = threadIdx.x;          // 256
    __shared__ unsigned int list[TK_CAP];
    __shared__ unsigned int hist[256];
    __shared__ int cnt, sB, sAbove, sL, sStrict, cA, cT;

    if (tid == 0) cnt = 0;
    hist[tid] = 0u;
    __syncthreads();

    const uint4* p4 = (const uint4*)(g_pre + (size_t)row * N_LAT);  // 4096 uint4
    for (int q = tid; q < N_LAT / 8; q += 256) {
        uint4 w = p4[q];
        unsigned int v[4] = {w.x, w.y, w.z, w.w};
#pragma unroll
        for (int j = 0; j < 4; j++) {
            unsigned int u0 = v[j] & 0xFFFFu;
            unsigned int u1 = v[j] >> 16;
            if (u0 >= 0x4000u && u0 < 0x8000u) {
                int p = atomicAdd(&cnt, 1);
                if (p < TK_CAP) list[p] = (u0 << 16) | (unsigned)(q * 8 + j * 2);
            }
            if (u1 >= 0x4000u && u1 < 0x8000u) {
                int p = atomicAdd(&cnt, 1);
                if (p < TK_CAP) list[p] = (u1 << 16) | (unsigned)(q * 8 + j * 2 + 1);
            }
        }
    }
    __syncthreads();
    const int n = cnt;

    if (n >= NCAND && n <= TK_CAP) {
        for (int i = tid; i < n; i += 256) atomicAdd(&hist[list[i] >> 24], 1u);
        __syncthreads();
        if (tid == 0) {
            int c = 0, b = 255;
            for (; b >= 0; b--) {
                if (c + (int)hist[b] >= NCAND) break;
                c += (int)hist[b];
            }
            sB = b; sAbove = c;
        }
        __syncthreads();
        const int B = sB, above = sAbove;
        hist[tid] = 0u;
        __syncthreads();
        for (int i = tid; i < n; i += 256) {
            unsigned int k = list[i] >> 16;
            if ((int)(k >> 8) == B) atomicAdd(&hist[k & 255u], 1u);
        }
        __syncthreads();
        if (tid == 0) {
            int c = above, l = 255;
            for (; l >= 0; l--) {
                if (c + (int)hist[l] >= NCAND) break;
                c += (int)hist[l];
            }
            sL = l; sStrict = c; cA = 0; cT = 0;
        }
        __syncthreads();
        const unsigned int kT = ((unsigned int)B << 8) | (unsigned int)sL;
        const int strict = sStrict;
        for (int i = tid; i < n; i += 256) {
            unsigned int k = list[i] >> 16;
            int idx = (int)(list[i] & 0xFFFFu);
            if (k > kT) {
                int s = atomicAdd(&cA, 1);
                g_cand[row * NCAND + s] = idx;
            } else if (k == kT) {
                int t = atomicAdd(&cT, 1);
                if (strict + t < NCAND)
                    g_cand[row * NCAND + strict + t] = idx;
            }
        }
        return;
    }

    // ---- fallback: full 3-pass histogram over the row (biased keys) ----
    __syncthreads();
    hist[tid] = 0u;
    __syncthreads();
    for (int q = tid; q < N_LAT / 8; q += 256) {
        uint4 w = p4[q];
        unsigned int v[4] = {w.x, w.y, w.z, w.w};
#pragma unroll
        for (int j = 0; j < 4; j++) {
            atomicAdd(&hist[bkey(v[j] & 0xFFFFu) >> 8], 1u);
            atomicAdd(&hist[bkey(v[j] >> 16) >> 8], 1u);
        }
    }
    __syncthreads();
    if (tid == 0) {
        int c = 0, b = 255;
        for (; b >= 0; b--) {
            if (c + (int)hist[b] >= NCAND) break;
            c += (int)hist[b];
        }
        sB = b; sAbove = c;
    }
    __syncthreads();
    const int B = sB, above = sAbove;
    hist[tid] = 0u;
    __syncthreads();
    for (int q = tid; q < N_LAT / 8; q += 256) {
        uint4 w = p4[q];
        unsigned int v[4] = {w.x, w.y, w.z, w.w};
#pragma unroll
        for (int j = 0; j < 4; j++) {
            unsigned int k0 = bkey(v[j] & 0xFFFFu);
            unsigned int k1 = bkey(v[j] >> 16);
            if ((int)(k0 >> 8) == B) atomicAdd(&hist[k0 & 255u], 1u);
            if ((int)(k1 >> 8) == B) atomicAdd(&hist[k1 & 255u], 1u);
        }
    }
    __syncthreads();
    if (tid == 0) {
        int c = above, l = 255;
        for (; l >= 0; l--) {
            if (c + (int)hist[l] >= NCAND) break;
            c += (int)hist[l];
        }
        sL = l; sStrict = c; cA = 0; cT = 0;
    }
    __syncthreads();
    const unsigned int kT = ((unsigned int)B << 8) | (unsigned int)sL;
    const int strict = sStrict;
    for (int q = tid; q < N_LAT / 8; q += 256) {
        uint4 w = p4[q];
        unsigned int v[4] = {w.x, w.y, w.z, w.w};
#pragma unroll
        for (int j = 0; j < 4; j++) {
#pragma unroll
            for (int h = 0; h < 2; h++) {
                unsigned int k = bkey(h ? (v[j] >> 16) : (v[j] & 0xFFFFu));
                if (k > kT) {
                    int s = atomicAdd(&cA, 1);
                    g_cand[row * NCAND + s] = q * 8 + j * 2 + h;
                } else if (k == kT) {
                    int t = atomicAdd(&cT, 1);
                    if (strict + t < NCAND)
                        g_cand[row * NCAND + strict + t] = q * 8 + j * 2 + h;
                }
            }
        }
    }
}

// ------------------------- exact fp32 rescore ------------------------------
__global__ __launch_bounds__(192) void k_rescore(const float* __restrict__ x,
                                                 const float* __restrict__ W_enc,
                                                 const float* __restrict__ b_enc,
                                                 const float* __restrict__ b_dec) {
    const int tid = threadIdx.x;
    const int row0 = blockIdx.x * 4;
    __shared__ __align__(16) float sx[4 * D_IN];
    for (int i = tid; i < 4 * D_IN; i += 192) {
        int r = i >> 11, col = i & (D_IN - 1);
        sx[i] = x[(size_t)(row0 + r) * D_IN + col] - b_dec[col];
    }
    __syncthreads();
    const int rl = tid / 48;
    const int ci = tid % 48;
    const int row = row0 + rl;
    const int c = g_cand[row * NCAND + ci];
    const float4* w4 = (const float4*)(W_enc + (size_t)c * D_IN);
    const float4* a4 = (const float4*)(sx + rl * D_IN);
    float s = 0.f;
#pragma unroll 4
    for (int q = 0; q < D_IN / 4; q++) {
        float4 w = w4[q];
        float4 a = a4[q];
        s = fmaf(a.x, w.x, s);
        s = fmaf(a.y, w.y, s);
        s = fmaf(a.z, w.z, s);
        s = fmaf(a.w, w.w, s);
    }
    float v = s + b_enc[c];
    g_cval[row * NCAND + ci] = v > 0.f ? v : 0.f;
}

// ------------------------- exact top-32 select -----------------------------
__global__ void k_select(float* __restrict__ out) {
    const int row = blockIdx.x;
    const int lane = threadIdx.x;
    float v0 = g_cval[row * NCAND + lane];
    int   i0 = g_cand[row * NCAND + lane];
    float v1 = (lane < NCAND - 32) ? g_cval[row * NCAND + 32 + lane] : -1e30f;
    int   i1 = (lane < NCAND - 32) ? g_cand[row * NCAND + 32 + lane] : 0x7FFFFFFF;

    for (int r = 0; r < KSEL; r++) {
        float bv; int bi;
        if (v0 > v1 || (v0 == v1 && i0 < i1)) { bv = v0; bi = i0; }
        else                                   { bv = v1; bi = i1; }
#pragma unroll
        for (int o = 16; o; o >>= 1) {
            float ov = __shfl_xor_sync(0xFFFFFFFFu, bv, o);
            int   oi = __shfl_xor_sync(0xFFFFFFFFu, bi, o);
            if (ov > bv || (ov == bv && oi < bi)) { bv = ov; bi = oi; }
        }
        if (lane == 0) {
            g_tact[row * KSEL + r] = bv;
            g_tidx[row * KSEL + r] = bi;
            out[OFF_ACT + row * KSEL + r] = bv;
            out[OFF_IDX + row * KSEL + r] = (float)bi;
        }
        if (i0 == bi) v0 = -1e30f;
        if (i1 == bi) v1 = -1e30f;
    }
}

// ------------------------- sparse decode + err^2 ---------------------------
__global__ void k_decode(const float* __restrict__ x, const float* __restrict__ W_dec,
                         const float* __restrict__ b_dec, float* __restrict__ out) {
    const int row = blockIdx.x;
    const int tid = threadIdx.x;
    __shared__ float sa[KSEL];
    __shared__ int   si[KSEL];
    __shared__ float red[256];
    if (tid < KSEL) { sa[tid] = g_tact[row * KSEL + tid]; si[tid] = g_tidx[row * KSEL + tid]; }
    __syncthreads();

    const float4* bd4 = (const float4*)b_dec;
    float4 a0 = bd4[tid];
    float4 a1 = bd4[tid + 256];
#pragma unroll 4
    for (int k = 0; k < KSEL; k++) {
        const float4* w4 = (const float4*)(W_dec + (size_t)si[k] * D_IN);
        float a = sa[k];
        float4 w0 = w4[tid], w1 = w4[tid + 256];
        a0.x += a * w0.x; a0.y += a * w0.y; a0.z += a * w0.z; a0.w += a * w0.w;
        a1.x += a * w1.x; a1.y += a * w1.y; a1.z += a * w1.z; a1.w += a * w1.w;
    }
    const float4* x4 = (const float4*)(x + (size_t)row * D_IN);
    float4 x0 = x4[tid], x1 = x4[tid + 256];
    ((float4*)out)[(size_t)row * (D_IN / 4) + tid] = a0;
    ((float4*)out)[(size_t)row * (D_IN / 4) + tid + 256] = a1;
    float e2 = 0.f;
    float d;
    d = x0.x - a0.x; e2 += d * d;  d = x0.y - a0.y; e2 += d * d;
    d = x0.z - a0.z; e2 += d * d;  d = x0.w - a0.w; e2 += d * d;
    d = x1.x - a1.x; e2 += d * d;  d = x1.y - a1.y; e2 += d * d;
    d = x1.z - a1.z; e2 += d * d;  d = x1.w - a1.w; e2 += d * d;

    red[tid] = e2;
    __syncthreads();
    for (int s = 128; s; s >>= 1) {
        if (tid < s) red[tid] += red[tid + s];
        __syncthreads();
    }
    if (tid == 0) atomicAdd(&g_err2, (double)red[0]);
}

// ------------------------- x stats: colsums + sum(x^2) ---------------------
__global__ void k_stats(const float* __restrict__ x) {
    const int b = blockIdx.x;
    const int tid = threadIdx.x;
    const float4* x4 = (const float4*)x;
    float4 a0 = make_float4(0.f, 0.f, 0.f, 0.f), a1 = a0;
    float sq = 0.f;
    for (int r = 0; r < 32; r++) {
        size_t base = (size_t)(b * 32 + r) * (D_IN / 4);
        float4 f0 = x4[base + tid], f1 = x4[base + tid + 256];
        a0.x += f0.x; a0.y += f0.y; a0.z += f0.z; a0.w += f0.w;
        a1.x += f1.x; a1.y += f1.y; a1.z += f1.z; a1.w += f1.w;
        sq += f0.x * f0.x + f0.y * f0.y + f0.z * f0.z + f0.w * f0.w;
        sq += f1.x * f1.x + f1.y * f1.y + f1.z * f1.z + f1.w * f1.w;
    }
    atomicAdd(&g_colsum[tid * 4 + 0], a0.x);
    atomicAdd(&g_colsum[tid * 4 + 1], a0.y);
    atomicAdd(&g_colsum[tid * 4 + 2], a0.z);
    atomicAdd(&g_colsum[tid * 4 + 3], a0.w);
    atomicAdd(&g_colsum[1024 + tid * 4 + 0], a1.x);
    atomicAdd(&g_colsum[1024 + tid * 4 + 1], a1.y);
    atomicAdd(&g_colsum[1024 + tid * 4 + 2], a1.z);
    atomicAdd(&g_colsum[1024 + tid * 4 + 3], a1.w);

    __shared__ float red[256];
    red[tid] = sq;
    __syncthreads();
    for (int s = 128; s; s >>= 1) {
        if (tid < s) red[tid] += red[tid + s];
        __syncthreads();
    }
    if (tid == 0) atomicAdd(&g_sumsq, (double)red[0]);
}

// ------------------------- finalize fvu ------------------------------------
__global__ void k_final(float* __restrict__ out) {
    const int tid = threadIdx.x;
    __shared__ float red[256];
    float s = 0.f;
    for (int c = tid; c < D_IN; c += 256) {
        float v = g_colsum[c];
        s += v * v;
    }
    red[tid] = s;
    __syncthreads();
    for (int q = 128; q; q >>= 1) {
        if (tid < q) red[tid] += red[tid + q];
        __syncthreads();
    }
    if (tid == 0) {
        double tv = g_sumsq - (double)red[0] / (double)B_ROWS;
        double fvu = g_err2 / tv;
        out[OFF_SC + 0] = (float)fvu;
        out[OFF_SC + 1] = 0.f;
        out[OFF_SC + 2] = 0.f;
    }
}

// ------------------------- launch ------------------------------------------
extern "C" void kernel_launch(void* const* d_in, const int* in_sizes, int n_in,
                              void* d_out, int out_size) {
    const float* x     = (const float*)d_in[0];
    const float* W_enc = (const float*)d_in[1];
    const float* b_enc = (const float*)d_in[2];
    const float* W_dec = (const float*)d_in[3];
    const float* b_dec = (const float*)d_in[4];
    float* out = (float*)d_out;

    cudaFuncSetAttribute(k_gemm, cudaFuncAttributeMaxDynamicSharedMemorySize, GEMM_SMEM);

    k_init<<<16, 256>>>();
    k_conv_x<<<(B_ROWS * (D_IN / 4)) / 256, 256>>>(x, b_dec);
    k_conv_w<<<(N_LAT * (D_IN / 4)) / 256, 256>>>(W_enc);
    k_gemm<<<dim3(B_ROWS / BM, N_LAT / BN), 128, GEMM_SMEM>>>(b_enc);
    k_topk<<<B_ROWS, 256>>>();
    k_rescore<<<B_ROWS / 4, 192>>>(x, W_enc, b_enc, b_dec);
    k_select<<<B_ROWS, 32>>>(out);
    k_decode<<<B_ROWS, 256>>>(x, W_dec, b_dec, out);
    k_stats<<<128, 256>>>(x);
    k_final<<<1, 256>>>(out);
}